// round 13
// baseline (speedup 1.0000x reference)
#include <cuda_runtime.h>
#include <math.h>

// ---------------------------------------------------------------------------
#define VR    16
#define DM    1024
#define NT    16
#define NL    3
#define KSEL  4
#define FDIM  32
#define NROWS 256
#define NENT  1024

#define RG     32          // rows per FFN block
#define KS     16          // k-depth per smem stage
#define CB     128         // cols per FFN block
#define KSPLIT 4
#define KRANGE (DM / KSPLIT)   // 256

typedef unsigned long long ull;

// ---------------------------------------------------------------------------
// Device scratch
// ---------------------------------------------------------------------------
__device__ float g_x[NROWS * DM];
__device__ float g_h[NENT * DM];
__device__ float g_part[(size_t)KSPLIT * NENT * DM];   // 16 MB split-K partials
__device__ float g_gate[NENT];
__device__ int   g_tile[NENT];
__device__ int   g_list[NL * NT * NROWS];
__device__ int   g_cnt[NL * NT];
__device__ float g_hs[NROWS * 512];
__device__ float g_hd[NROWS * 512];
__device__ float g_table[NROWS * 11];

// ---------------------------------------------------------------------------
__device__ __forceinline__ float gelu_erf(float x) {
    return 0.5f * x * (1.0f + erff(x * 0.70710678118654752440f));
}

__device__ __forceinline__ ull fma2(ull a, ull b, ull c) {
    ull d;
    asm("fma.rn.f32x2 %0, %1, %2, %3;" : "=l"(d) : "l"(a), "l"(b), "l"(c));
    return d;
}

__device__ __forceinline__ ull pack2(float x) {
    union { float2 f; ull u; } v;
    v.f = make_float2(x, x);
    return v.u;
}

__device__ __forceinline__ float ullo(ull u) {
    union { ull u; float2 f; } v; v.u = u; return v.f.x;
}
__device__ __forceinline__ float ulhi(ull u) {
    union { ull u; float2 f; } v; v.u = u; return v.f.y;
}

__device__ __forceinline__ void cp16(unsigned int dst, const void* src) {
    asm volatile("cp.async.ca.shared.global [%0], [%1], 16;"
                 :: "r"(dst), "l"(src));
}
#define CP_COMMIT() asm volatile("cp.async.commit_group;")
#define CP_WAIT0()  asm volatile("cp.async.wait_group 0;")

__device__ __forceinline__ float blockReduceSum(float v, float* red) {
    int tid = threadIdx.x;
    int lane = tid & 31, wid = tid >> 5;
#pragma unroll
    for (int o = 16; o > 0; o >>= 1) v += __shfl_down_sync(0xffffffffu, v, o);
    if (lane == 0) red[wid] = v;
    __syncthreads();
    int nw = (blockDim.x + 31) >> 5;
    if (tid < 32) {
        v = (tid < nw) ? red[tid] : 0.0f;
#pragma unroll
        for (int o = 16; o > 0; o >>= 1) v += __shfl_down_sync(0xffffffffu, v, o);
        if (tid == 0) red[0] = v;
    }
    __syncthreads();
    float r = red[0];
    __syncthreads();
    return r;
}

// ---------------------------------------------------------------------------
// 1) Encode (+ zero counters)
// ---------------------------------------------------------------------------
__global__ void k_encode(const float* __restrict__ Win,
                         const float* __restrict__ bin_,
                         const float* __restrict__ gamma,
                         const float* __restrict__ beta) {
    int r = blockIdx.x;
    int tid = threadIdx.x;
    __shared__ float feats[FDIM];
    __shared__ float red[33];

    if (blockIdx.x == 0 && tid < NL * NT) g_cnt[tid] = 0;

    if (tid < FDIM) {
        int which = tid >> 4;
        int idx   = tid & 15;
        int isCos = idx >> 3;
        int j     = idx & 7;
        int val   = which ? (r & 15) : (r >> 4);
        float xn  = (float)val * (float)(2.0 * M_PI / (double)VR);
        float ang = xn * exp2f((float)j);
        feats[tid] = isCos ? cosf(ang) : sinf(ang);
    }
    __syncthreads();

    int f0 = tid * 4;
    float4 acc = make_float4(bin_[f0], bin_[f0 + 1], bin_[f0 + 2], bin_[f0 + 3]);
#pragma unroll
    for (int fd = 0; fd < FDIM; fd++) {
        float fv = feats[fd];
        float4 w = *(const float4*)&Win[fd * DM + f0];
        acc.x += fv * w.x; acc.y += fv * w.y; acc.z += fv * w.z; acc.w += fv * w.w;
    }

    float s = acc.x + acc.y + acc.z + acc.w;
    float mean = blockReduceSum(s, red) * (1.0f / DM);
    float dx = acc.x - mean, dy = acc.y - mean, dz = acc.z - mean, dw = acc.w - mean;
    float ss = dx * dx + dy * dy + dz * dz + dw * dw;
    float var = blockReduceSum(ss, red) * (1.0f / DM);
    float inv = rsqrtf(var + 1e-5f);

    float4 o;
    o.x = gelu_erf(dx * inv * gamma[f0 + 0] + beta[f0 + 0]);
    o.y = gelu_erf(dy * inv * gamma[f0 + 1] + beta[f0 + 1]);
    o.z = gelu_erf(dz * inv * gamma[f0 + 2] + beta[f0 + 2]);
    o.w = gelu_erf(dw * inv * gamma[f0 + 3] + beta[f0 + 3]);
    *(float4*)&g_x[r * DM + f0] = o;
}

// ---------------------------------------------------------------------------
// 2) Router
// ---------------------------------------------------------------------------
__global__ void k_router(const float* __restrict__ Wr_l, int l) {
    int r = blockIdx.x;
    int tid = threadIdx.x;
    int w = tid >> 5, lane = tid & 31;
    __shared__ float logits[NT];

    float s = 0.0f;
    const float* xr = &g_x[r * DM];
#pragma unroll 8
    for (int d = lane; d < DM; d += 32)
        s += xr[d] * Wr_l[d * NT + w];
#pragma unroll
    for (int o = 16; o > 0; o >>= 1) s += __shfl_down_sync(0xffffffffu, s, o);
    if (lane == 0) logits[w] = s;
    __syncthreads();

    if (tid == 0) {
        float mx = logits[0];
#pragma unroll
        for (int t = 1; t < NT; t++) mx = fmaxf(mx, logits[t]);
        float e[NT], sum = 0.0f;
#pragma unroll
        for (int t = 0; t < NT; t++) { e[t] = expf(logits[t] - mx); sum += e[t]; }
        float invs = 1.0f / sum;
        float p[NT];
#pragma unroll
        for (int t = 0; t < NT; t++) p[t] = e[t] * invs;

        bool used[NT];
#pragma unroll
        for (int t = 0; t < NT; t++) used[t] = false;
#pragma unroll
        for (int k = 0; k < KSEL; k++) {
            float bv = -1.0f; int bi = 0;
#pragma unroll
            for (int t = 0; t < NT; t++)
                if (!used[t] && p[t] > bv) { bv = p[t]; bi = t; }
            used[bi] = true;
            int ent = (r << 2) | k;
            g_gate[ent] = bv;
            g_tile[ent] = bi;
            int pos = atomicAdd(&g_cnt[l * NT + bi], 1);
            g_list[(l * NT + bi) * NROWS + pos] = ent;
        }
    }
}

// ---------------------------------------------------------------------------
// 3) FFN GEMM: split-K x4, 32x128 block tile, KS=16 stages, cp.async W
//    staging, 4x4 thread tile, FFMA2 with register-side x duplication
//    (x stored in smem as PLAIN floats -> 1 LDS.128 instead of 2).
// grid (8 colblocks, 16 tiles, 8 rowgroups * 4 ksplits), block 256
// ---------------------------------------------------------------------------
template <int STAGE>
__global__ __launch_bounds__(256, 3)
void k_ffn(const float* __restrict__ W, int l) {
    const int t   = blockIdx.y;
    const int cnt = g_cnt[l * NT + t];
    const int zg  = blockIdx.z >> 2;
    const int ks  = blockIdx.z & 3;
    const int base = zg * RG;
    if (base >= cnt) return;
    const int f0 = blockIdx.x * CB;
    const int k0 = ks * KRANGE;
    const float* __restrict__ Wt = W + (size_t)t * DM * DM;

    __shared__ int rowk[RG];
    __shared__ __align__(16) float xs[2][KS][RG];    // 4 KB (plain floats)
    __shared__ __align__(16) float ws[2][KS][CB];    // 16 KB

    const int tid = threadIdx.x;
    if (tid < RG) {
        int e = base + tid;
        rowk[tid] = (e < cnt) ? g_list[(l * NT + t) * NROWS + e] : -1;
    }
    __syncthreads();

    // compute mapping: 8 warps; warp tile 16 rows x 32 cols; thread 4 rows x 4 cols
    const int lane  = tid & 31;
    const int wrp   = tid >> 5;
    const int rhalf = wrp & 1;
    const int cq    = wrp >> 1;
    const int tx    = lane & 7;
    const int ly    = lane >> 3;
    const int rowbase = (rhalf << 4) + (ly << 2);
    const int col0    = (cq << 5) + (tx << 2);

    // W cp.async mapping: stage = 16 k-rows x 128 cols = 512 float4; 2/thread.
    const int wrow0 = tid >> 5;                 // 0..7
    const int wc4   = (tid & 31) << 2;          // 0..124
    const unsigned int wdstA =
        (unsigned int)__cvta_generic_to_shared(&ws[0][wrow0][wc4]);
    const unsigned int wdstB =
        (unsigned int)__cvta_generic_to_shared(&ws[1][wrow0][wc4]);
    const float* wsrc = Wt + (size_t)(k0 + wrow0) * DM + f0 + wc4;
    const unsigned int wjstride = 8 * CB * 4;   // 8 smem rows, bytes

    // x loader: threads 0..127 load one float4 (k-direction) per stage
    const bool xload = tid < 128;
    const int mrow = tid & 31;
    const int mkq  = ((tid >> 5) & 3) << 2;     // 0,4,8,12
    const float* myrow;
    {
        int el = rowk[mrow];
        int ridx = 0;
        if (el >= 0) ridx = (STAGE == 1) ? (el >> 2) : el;
        myrow = ((STAGE == 1) ? g_x : g_h) + (size_t)ridx * DM + k0;
    }

    ull acc[4][2];
#pragma unroll
    for (int i = 0; i < 4; i++) { acc[i][0] = 0ull; acc[i][1] = 0ull; }

    // prologue: stage 0
#pragma unroll
    for (int j = 0; j < 2; j++)
        cp16(wdstA + j * wjstride, wsrc + (size_t)(8 * j) * DM);
    CP_COMMIT();
    if (xload) {
        float4 xr = *(const float4*)(myrow + mkq);
        xs[0][mkq + 0][mrow] = xr.x;
        xs[0][mkq + 1][mrow] = xr.y;
        xs[0][mkq + 2][mrow] = xr.z;
        xs[0][mkq + 3][mrow] = xr.w;
    }
    CP_WAIT0();
    __syncthreads();

    for (int kb = 0; kb < KRANGE / KS; kb++) {
        const int buf = kb & 1;
        float4 xr;
        const bool more = (kb + 1 < KRANGE / KS);
        if (more) {
            const int d0 = (kb + 1) * KS;
            const unsigned int nd = buf ? wdstA : wdstB;
            const float* ns = wsrc + (size_t)d0 * DM;
#pragma unroll
            for (int j = 0; j < 2; j++)
                cp16(nd + j * wjstride, ns + (size_t)(8 * j) * DM);
            CP_COMMIT();
            if (xload) xr = *(const float4*)(myrow + d0 + mkq);
        }
#pragma unroll
        for (int kk = 0; kk < KS; kk++) {
            union { float4 f; ull u[2]; } wa;
            wa.f = *(const float4*)&ws[buf][kk][col0];
            float4 xv = *(const float4*)&xs[buf][kk][rowbase];
            ull x0 = pack2(xv.x);
            ull x1 = pack2(xv.y);
            ull x2 = pack2(xv.z);
            ull x3 = pack2(xv.w);
            acc[0][0] = fma2(x0, wa.u[0], acc[0][0]);
            acc[0][1] = fma2(x0, wa.u[1], acc[0][1]);
            acc[1][0] = fma2(x1, wa.u[0], acc[1][0]);
            acc[1][1] = fma2(x1, wa.u[1], acc[1][1]);
            acc[2][0] = fma2(x2, wa.u[0], acc[2][0]);
            acc[2][1] = fma2(x2, wa.u[1], acc[2][1]);
            acc[3][0] = fma2(x3, wa.u[0], acc[3][0]);
            acc[3][1] = fma2(x3, wa.u[1], acc[3][1]);
        }
        if (more) {
            const int nb = buf ^ 1;
            if (xload) {
                xs[nb][mkq + 0][mrow] = xr.x;
                xs[nb][mkq + 1][mrow] = xr.y;
                xs[nb][mkq + 2][mrow] = xr.z;
                xs[nb][mkq + 3][mrow] = xr.w;
            }
            CP_WAIT0();
        }
        __syncthreads();
    }

    // epilogue: write bias-free partials
#pragma unroll
    for (int i = 0; i < 4; i++) {
        int ee = rowk[rowbase + i];
        if (ee < 0) continue;
        float* op = g_part + ((size_t)ks * NENT + ee) * DM + f0;
        *(float4*)&op[col0] = make_float4(ullo(acc[i][0]), ulhi(acc[i][0]),
                                          ullo(acc[i][1]), ulhi(acc[i][1]));
    }
}

// ---------------------------------------------------------------------------
// 4) Reduce stage-1 partials: h = gelu(sum_s part + b1[tile])
// grid 1024, block 256
// ---------------------------------------------------------------------------
__global__ void k_red1(const float* __restrict__ b1l) {
    int ent = blockIdx.x;
    int tid = threadIdx.x;
    int t = g_tile[ent];
    int c4 = tid * 4;
    float4 acc = *(const float4*)&b1l[t * DM + c4];
#pragma unroll
    for (int s = 0; s < KSPLIT; s++) {
        float4 p = *(const float4*)&g_part[((size_t)s * NENT + ent) * DM + c4];
        acc.x += p.x; acc.y += p.y; acc.z += p.z; acc.w += p.w;
    }
    float4 o;
    o.x = gelu_erf(acc.x); o.y = gelu_erf(acc.y);
    o.z = gelu_erf(acc.z); o.w = gelu_erf(acc.w);
    *(float4*)&g_h[(size_t)ent * DM + c4] = o;
}

// ---------------------------------------------------------------------------
// 5) Combine (fused stage-2 reduce + bias + gate + residual + LN)
// grid 256, block 256
// ---------------------------------------------------------------------------
__global__ void k_combine(const float* __restrict__ gamma,
                          const float* __restrict__ beta,
                          const float* __restrict__ b2l) {
    int r = blockIdx.x;
    int tid = threadIdx.x;
    __shared__ float red[33];
    int c4 = tid * 4;

    float4 v = *(const float4*)&g_x[r * DM + c4];
#pragma unroll
    for (int k = 0; k < KSEL; k++) {
        int ent = r * 4 + k;
        int t = g_tile[ent];
        float gate = g_gate[ent];
        float4 acc = *(const float4*)&b2l[t * DM + c4];
#pragma unroll
        for (int s = 0; s < KSPLIT; s++) {
            float4 p = *(const float4*)&g_part[((size_t)s * NENT + ent) * DM + c4];
            acc.x += p.x; acc.y += p.y; acc.z += p.z; acc.w += p.w;
        }
        v.x += gate * acc.x; v.y += gate * acc.y;
        v.z += gate * acc.z; v.w += gate * acc.w;
    }
    float s = v.x + v.y + v.z + v.w;
    float mean = blockReduceSum(s, red) * (1.0f / DM);
    float dx = v.x - mean, dy = v.y - mean, dz = v.z - mean, dw = v.w - mean;
    float ss = dx * dx + dy * dy + dz * dz + dw * dw;
    float var = blockReduceSum(ss, red) * (1.0f / DM);
    float inv = rsqrtf(var + 1e-5f);

    float4 o;
    o.x = dx * inv * gamma[c4 + 0] + beta[c4 + 0];
    o.y = dy * inv * gamma[c4 + 1] + beta[c4 + 1];
    o.z = dz * inv * gamma[c4 + 2] + beta[c4 + 2];
    o.w = dw * inv * gamma[c4 + 3] + beta[c4 + 3];
    *(float4*)&g_x[r * DM + c4] = o;
}

// ---------------------------------------------------------------------------
// 6) Heads layer-1
// ---------------------------------------------------------------------------
__global__ __launch_bounds__(256)
void k_heads1(const float* __restrict__ Ws1, const float* __restrict__ bs1,
              const float* __restrict__ Wd1, const float* __restrict__ bd1) {
    __shared__ float xsh[8][DM];
    int tid = threadIdx.x;
    int rbase = blockIdx.x * 8;

#pragma unroll
    for (int i = 0; i < 8; i++) {
        int idx = tid + i * 256;
        int row = idx >> 8;
        int c4 = (idx & 255) * 4;
        *(float4*)&xsh[row][c4] = *(const float4*)&g_x[(rbase + row) * DM + c4];
    }
    __syncthreads();

    const bool sumhead = tid < 128;
    const int j = blockIdx.y * 128 + (sumhead ? tid : tid - 128);
    const float* __restrict__ W = sumhead ? Ws1 : Wd1;
    float* __restrict__ outp = sumhead ? g_hs : g_hd;
    float bb = sumhead ? bs1[j] : bd1[j];

    float acc[8];
#pragma unroll
    for (int rr = 0; rr < 8; rr++) acc[rr] = bb;

    for (int d = 0; d < DM; d += 4) {
        float w0 = W[(d + 0) * 512 + j];
        float w1 = W[(d + 1) * 512 + j];
        float w2 = W[(d + 2) * 512 + j];
        float w3 = W[(d + 3) * 512 + j];
#pragma unroll
        for (int rr = 0; rr < 8; rr++) {
            float4 xv = *(const float4*)&xsh[rr][d];
            acc[rr] += xv.x * w0 + xv.y * w1 + xv.z * w2 + xv.w * w3;
        }
    }
#pragma unroll
    for (int rr = 0; rr < 8; rr++)
        outp[(rbase + rr) * 512 + j] = gelu_erf(acc[rr]);
}

// ---------------------------------------------------------------------------
// 7) Heads layer-2
// ---------------------------------------------------------------------------
__global__ void k_heads2(const float* __restrict__ Ws2, const float* __restrict__ bs2,
                         const float* __restrict__ Wd2, const float* __restrict__ bd2) {
    int r = blockIdx.x;
    int tid = threadIdx.x;
    int c = tid >> 5, lane = tid & 31;
    if (c >= 11) return;
    const float* h;
    const float* W;
    float bb; int nc, cc;
    if (c < 5) { h = g_hs + r * 512; W = Ws2; nc = 5; cc = c;     bb = bs2[c]; }
    else       { h = g_hd + r * 512; W = Wd2; nc = 6; cc = c - 5; bb = bd2[c - 5]; }
    float s = 0.0f;
#pragma unroll 4
    for (int f = lane; f < 512; f += 32) s += h[f] * W[f * nc + cc];
#pragma unroll
    for (int o = 16; o > 0; o >>= 1) s += __shfl_down_sync(0xffffffffu, s, o);
    if (lane == 0) g_table[r * 11 + c] = s + bb;
}

// ---------------------------------------------------------------------------
// 8) Gather
// ---------------------------------------------------------------------------
__global__ void k_output(const int* __restrict__ a, const int* __restrict__ b,
                         float* __restrict__ out, int total) {
    int idx = blockIdx.x * blockDim.x + threadIdx.x;
    if (idx >= total) return;
    int i = idx / 11;
    int c = idx - i * 11;
    int r = a[i] * 16 + b[i];
    out[idx] = g_table[r * 11 + c];
}

// ---------------------------------------------------------------------------
extern "C" void kernel_launch(void* const* d_in, const int* in_sizes, int n_in,
                              void* d_out, int out_size) {
    const int*   a      = (const int*)d_in[0];
    const int*   b      = (const int*)d_in[1];
    const float* Win    = (const float*)d_in[2];
    const float* bin_   = (const float*)d_in[3];
    const float* g_in   = (const float*)d_in[4];
    const float* b_ln   = (const float*)d_in[5];
    const float* Wr     = (const float*)d_in[6];
    const float* W1     = (const float*)d_in[7];
    const float* b1     = (const float*)d_in[8];
    const float* W2     = (const float*)d_in[9];
    const float* b2     = (const float*)d_in[10];
    const float* g_l    = (const float*)d_in[11];
    const float* b_l    = (const float*)d_in[12];
    const float* Ws1    = (const float*)d_in[13];
    const float* bs1    = (const float*)d_in[14];
    const float* Ws2    = (const float*)d_in[15];
    const float* bs2    = (const float*)d_in[16];
    const float* Wd1    = (const float*)d_in[17];
    const float* bd1    = (const float*)d_in[18];
    const float* Wd2    = (const float*)d_in[19];
    const float* bd2    = (const float*)d_in[20];
    float* out = (float*)d_out;

    (void)in_sizes; (void)n_in;

    k_encode<<<NROWS, 256>>>(Win, bin_, g_in, b_ln);

    for (int l = 0; l < NL; l++) {
        k_router<<<NROWS, 512>>>(Wr + (size_t)l * DM * NT, l);
        dim3 gffn(DM / CB, NT, (NROWS / RG) * KSPLIT);
        k_ffn<1><<<gffn, 256>>>(W1 + (size_t)l * NT * DM * DM, l);
        k_red1<<<NENT, 256>>>(b1 + (size_t)l * NT * DM);
        k_ffn<2><<<gffn, 256>>>(W2 + (size_t)l * NT * DM * DM, l);
        k_combine<<<NROWS, 256>>>(g_l + (size_t)l * DM, b_l + (size_t)l * DM,
                                  b2 + (size_t)l * NT * DM);
    }

    k_heads1<<<dim3(NROWS / 8, 4), 256>>>(Ws1, bs1, Wd1, bd1);
    k_heads2<<<NROWS, 352>>>(Ws2, bs2, Wd2, bd2);

    int total = out_size;
    k_output<<<(total + 255) / 256, 256>>>(a, b, out, total);
}

// round 15
// speedup vs baseline: 1.3188x; 1.3188x over previous
#include <cuda_runtime.h>
#include <math.h>

// ---------------------------------------------------------------------------
#define VR    16
#define DM    1024
#define NT    16
#define NL    3
#define KSEL  4
#define FDIM  32
#define NROWS 256
#define NENT  1024

#define RG     32          // rows per FFN block
#define KS     16          // k-depth per smem stage
#define CB     128         // cols per FFN block
#define KSPLIT 4
#define KRANGE (DM / KSPLIT)   // 256

typedef unsigned long long ull;

// ---------------------------------------------------------------------------
// Device scratch
// ---------------------------------------------------------------------------
__device__ float g_x[NROWS * DM];
__device__ float g_h[NENT * DM];
__device__ float g_part[(size_t)KSPLIT * NENT * DM];   // 16 MB split-K partials
__device__ float g_gate[NENT];
__device__ int   g_tile[NENT];
__device__ int   g_list[NL * NT * NROWS];
__device__ int   g_cnt[NL * NT];
__device__ float g_hs[NROWS * 512];
__device__ float g_hd[NROWS * 512];
__device__ float g_table[NROWS * 11];

// ---------------------------------------------------------------------------
__device__ __forceinline__ float gelu_erf(float x) {
    return 0.5f * x * (1.0f + erff(x * 0.70710678118654752440f));
}

__device__ __forceinline__ ull fma2(ull a, ull b, ull c) {
    ull d;
    asm("fma.rn.f32x2 %0, %1, %2, %3;" : "=l"(d) : "l"(a), "l"(b), "l"(c));
    return d;
}

__device__ __forceinline__ ull pack2(float x) {
    union { float2 f; ull u; } v;
    v.f = make_float2(x, x);
    return v.u;
}

__device__ __forceinline__ float ullo(ull u) {
    union { ull u; float2 f; } v; v.u = u; return v.f.x;
}
__device__ __forceinline__ float ulhi(ull u) {
    union { ull u; float2 f; } v; v.u = u; return v.f.y;
}

__device__ __forceinline__ void cp16(unsigned int dst, const void* src) {
    asm volatile("cp.async.ca.shared.global [%0], [%1], 16;"
                 :: "r"(dst), "l"(src));
}
#define CP_COMMIT() asm volatile("cp.async.commit_group;")
#define CP_WAIT0()  asm volatile("cp.async.wait_group 0;")

__device__ __forceinline__ float blockReduceSum(float v, float* red) {
    int tid = threadIdx.x;
    int lane = tid & 31, wid = tid >> 5;
#pragma unroll
    for (int o = 16; o > 0; o >>= 1) v += __shfl_down_sync(0xffffffffu, v, o);
    if (lane == 0) red[wid] = v;
    __syncthreads();
    int nw = (blockDim.x + 31) >> 5;
    if (tid < 32) {
        v = (tid < nw) ? red[tid] : 0.0f;
#pragma unroll
        for (int o = 16; o > 0; o >>= 1) v += __shfl_down_sync(0xffffffffu, v, o);
        if (tid == 0) red[0] = v;
    }
    __syncthreads();
    float r = red[0];
    __syncthreads();
    return r;
}

// ---------------------------------------------------------------------------
// Fused router: block computes routing for row r at layer l from xrow (smem).
// 256 threads = 8 warps; each warp computes 2 tile logits.
// ---------------------------------------------------------------------------
__device__ void route_row(int r, int l, const float* __restrict__ Wr_l,
                          const float* xrow, float* logits) {
    int tid = threadIdx.x;
    int w = tid >> 5, lane = tid & 31;
    int t0 = 2 * w, t1 = 2 * w + 1;
    float s0 = 0.0f, s1 = 0.0f;
#pragma unroll 4
    for (int d = lane; d < DM; d += 32) {
        float xv = xrow[d];
        s0 += xv * Wr_l[d * NT + t0];
        s1 += xv * Wr_l[d * NT + t1];
    }
#pragma unroll
    for (int o = 16; o > 0; o >>= 1) {
        s0 += __shfl_down_sync(0xffffffffu, s0, o);
        s1 += __shfl_down_sync(0xffffffffu, s1, o);
    }
    if (lane == 0) { logits[t0] = s0; logits[t1] = s1; }
    __syncthreads();

    if (tid == 0) {
        float mx = logits[0];
#pragma unroll
        for (int t = 1; t < NT; t++) mx = fmaxf(mx, logits[t]);
        float e[NT], sum = 0.0f;
#pragma unroll
        for (int t = 0; t < NT; t++) { e[t] = expf(logits[t] - mx); sum += e[t]; }
        float invs = 1.0f / sum;
        float p[NT];
#pragma unroll
        for (int t = 0; t < NT; t++) p[t] = e[t] * invs;

        bool used[NT];
#pragma unroll
        for (int t = 0; t < NT; t++) used[t] = false;
#pragma unroll
        for (int k = 0; k < KSEL; k++) {
            float bv = -1.0f; int bi = 0;
#pragma unroll
            for (int t = 0; t < NT; t++)
                if (!used[t] && p[t] > bv) { bv = p[t]; bi = t; }
            used[bi] = true;
            int ent = (r << 2) | k;
            g_gate[ent] = bv;
            g_tile[ent] = bi;
            int pos = atomicAdd(&g_cnt[l * NT + bi], 1);
            g_list[(l * NT + bi) * NROWS + pos] = ent;
        }
    }
}

// ---------------------------------------------------------------------------
// 0) Zero counters (runs before encode)
// ---------------------------------------------------------------------------
__global__ void k_zero() {
    if (threadIdx.x < NL * NT) g_cnt[threadIdx.x] = 0;
}

// ---------------------------------------------------------------------------
// 1) Encode + fused layer-0 routing
// ---------------------------------------------------------------------------
__global__ void k_encode(const float* __restrict__ Win,
                         const float* __restrict__ bin_,
                         const float* __restrict__ gamma,
                         const float* __restrict__ beta,
                         const float* __restrict__ Wr0) {
    int r = blockIdx.x;
    int tid = threadIdx.x;
    __shared__ __align__(16) float feats[FDIM];
    __shared__ __align__(16) float red[36];
    __shared__ __align__(16) float xrow[DM];
    __shared__ __align__(16) float logits[NT];

    if (tid < FDIM) {
        int which = tid >> 4;
        int idx   = tid & 15;
        int isCos = idx >> 3;
        int j     = idx & 7;
        int val   = which ? (r & 15) : (r >> 4);
        float xn  = (float)val * (float)(2.0 * M_PI / (double)VR);
        float ang = xn * exp2f((float)j);
        feats[tid] = isCos ? cosf(ang) : sinf(ang);
    }
    __syncthreads();

    int f0 = tid * 4;
    float4 acc = make_float4(bin_[f0], bin_[f0 + 1], bin_[f0 + 2], bin_[f0 + 3]);
#pragma unroll
    for (int fd = 0; fd < FDIM; fd++) {
        float fv = feats[fd];
        float4 w = *(const float4*)&Win[fd * DM + f0];
        acc.x += fv * w.x; acc.y += fv * w.y; acc.z += fv * w.z; acc.w += fv * w.w;
    }

    float s = acc.x + acc.y + acc.z + acc.w;
    float mean = blockReduceSum(s, red) * (1.0f / DM);
    float dx = acc.x - mean, dy = acc.y - mean, dz = acc.z - mean, dw = acc.w - mean;
    float ss = dx * dx + dy * dy + dz * dz + dw * dw;
    float var = blockReduceSum(ss, red) * (1.0f / DM);
    float inv = rsqrtf(var + 1e-5f);

    float4 o;
    o.x = gelu_erf(dx * inv * gamma[f0 + 0] + beta[f0 + 0]);
    o.y = gelu_erf(dy * inv * gamma[f0 + 1] + beta[f0 + 1]);
    o.z = gelu_erf(dz * inv * gamma[f0 + 2] + beta[f0 + 2]);
    o.w = gelu_erf(dw * inv * gamma[f0 + 3] + beta[f0 + 3]);
    *(float4*)&g_x[r * DM + f0] = o;
    *(float4*)&xrow[f0] = o;
    __syncthreads();

    route_row(r, 0, Wr0, xrow, logits);
}

// ---------------------------------------------------------------------------
// 2) FFN GEMM: split-K x4, 32x128 block tile, KS=16 stages, cp.async W
//    staging, 4x4 thread tile, FFMA2 (x pre-duplicated into f32x2 smem).
//    [round-8 proven version, unchanged]
// grid (8 colblocks, 16 tiles, 8 rowgroups * 4 ksplits), block 256
// ---------------------------------------------------------------------------
template <int STAGE>
__global__ __launch_bounds__(256, 3)
void k_ffn(const float* __restrict__ W, int l) {
    const int t   = blockIdx.y;
    const int cnt = g_cnt[l * NT + t];
    const int zg  = blockIdx.z >> 2;
    const int ks  = blockIdx.z & 3;
    const int base = zg * RG;
    if (base >= cnt) return;
    const int f0 = blockIdx.x * CB;
    const int k0 = ks * KRANGE;
    const float* __restrict__ Wt = W + (size_t)t * DM * DM;

    __shared__ int rowk[RG];
    __shared__ __align__(16) ull   xs2[2][KS][RG];   // 8 KB
    __shared__ __align__(16) float ws[2][KS][CB];    // 16 KB

    const int tid = threadIdx.x;
    if (tid < RG) {
        int e = base + tid;
        rowk[tid] = (e < cnt) ? g_list[(l * NT + t) * NROWS + e] : -1;
    }
    __syncthreads();

    const int lane  = tid & 31;
    const int wrp   = tid >> 5;
    const int rhalf = wrp & 1;
    const int cq    = wrp >> 1;
    const int tx    = lane & 7;
    const int ly    = lane >> 3;
    const int rowbase = (rhalf << 4) + (ly << 2);
    const int col0    = (cq << 5) + (tx << 2);

    const int wrow0 = tid >> 5;
    const int wc4   = (tid & 31) << 2;
    const unsigned int wdstA =
        (unsigned int)__cvta_generic_to_shared(&ws[0][wrow0][wc4]);
    const unsigned int wdstB =
        (unsigned int)__cvta_generic_to_shared(&ws[1][wrow0][wc4]);
    const float* wsrc = Wt + (size_t)(k0 + wrow0) * DM + f0 + wc4;
    const unsigned int wjstride = 8 * CB * 4;

    const bool xload = tid < 128;
    const int mrow = tid & 31;
    const int mkq  = ((tid >> 5) & 3) << 2;
    const float* myrow;
    {
        int el = rowk[mrow];
        int ridx = 0;
        if (el >= 0) ridx = (STAGE == 1) ? (el >> 2) : el;
        myrow = ((STAGE == 1) ? g_x : g_h) + (size_t)ridx * DM + k0;
    }

    ull acc[4][2];
#pragma unroll
    for (int i = 0; i < 4; i++) { acc[i][0] = 0ull; acc[i][1] = 0ull; }

#pragma unroll
    for (int j = 0; j < 2; j++)
        cp16(wdstA + j * wjstride, wsrc + (size_t)(8 * j) * DM);
    CP_COMMIT();
    if (xload) {
        float4 xr = *(const float4*)(myrow + mkq);
        xs2[0][mkq + 0][mrow] = pack2(xr.x);
        xs2[0][mkq + 1][mrow] = pack2(xr.y);
        xs2[0][mkq + 2][mrow] = pack2(xr.z);
        xs2[0][mkq + 3][mrow] = pack2(xr.w);
    }
    CP_WAIT0();
    __syncthreads();

    for (int kb = 0; kb < KRANGE / KS; kb++) {
        const int buf = kb & 1;
        float4 xr;
        const bool more = (kb + 1 < KRANGE / KS);
        if (more) {
            const int d0 = (kb + 1) * KS;
            const unsigned int nd = buf ? wdstA : wdstB;
            const float* ns = wsrc + (size_t)d0 * DM;
#pragma unroll
            for (int j = 0; j < 2; j++)
                cp16(nd + j * wjstride, ns + (size_t)(8 * j) * DM);
            CP_COMMIT();
            if (xload) xr = *(const float4*)(myrow + d0 + mkq);
        }
#pragma unroll
        for (int kk = 0; kk < KS; kk++) {
            union { float4 f; ull u[2]; } wa;
            wa.f = *(const float4*)&ws[buf][kk][col0];
            ulonglong2 xp0 = *(const ulonglong2*)&xs2[buf][kk][rowbase];
            ulonglong2 xp1 = *(const ulonglong2*)&xs2[buf][kk][rowbase + 2];
            acc[0][0] = fma2(xp0.x, wa.u[0], acc[0][0]);
            acc[0][1] = fma2(xp0.x, wa.u[1], acc[0][1]);
            acc[1][0] = fma2(xp0.y, wa.u[0], acc[1][0]);
            acc[1][1] = fma2(xp0.y, wa.u[1], acc[1][1]);
            acc[2][0] = fma2(xp1.x, wa.u[0], acc[2][0]);
            acc[2][1] = fma2(xp1.x, wa.u[1], acc[2][1]);
            acc[3][0] = fma2(xp1.y, wa.u[0], acc[3][0]);
            acc[3][1] = fma2(xp1.y, wa.u[1], acc[3][1]);
        }
        if (more) {
            const int nb = buf ^ 1;
            if (xload) {
                xs2[nb][mkq + 0][mrow] = pack2(xr.x);
                xs2[nb][mkq + 1][mrow] = pack2(xr.y);
                xs2[nb][mkq + 2][mrow] = pack2(xr.z);
                xs2[nb][mkq + 3][mrow] = pack2(xr.w);
            }
            CP_WAIT0();
        }
        __syncthreads();
    }

#pragma unroll
    for (int i = 0; i < 4; i++) {
        int ee = rowk[rowbase + i];
        if (ee < 0) continue;
        float* op = g_part + ((size_t)ks * NENT + ee) * DM + f0;
        *(float4*)&op[col0] = make_float4(ullo(acc[i][0]), ulhi(acc[i][0]),
                                          ullo(acc[i][1]), ulhi(acc[i][1]));
    }
}

// ---------------------------------------------------------------------------
// 3) Reduce stage-1 partials: h = gelu(sum_s part + b1[tile])
// ---------------------------------------------------------------------------
__global__ void k_red1(const float* __restrict__ b1l) {
    int ent = blockIdx.x;
    int tid = threadIdx.x;
    int t = g_tile[ent];
    int c4 = tid * 4;
    float4 acc = *(const float4*)&b1l[t * DM + c4];
#pragma unroll
    for (int s = 0; s < KSPLIT; s++) {
        float4 p = *(const float4*)&g_part[((size_t)s * NENT + ent) * DM + c4];
        acc.x += p.x; acc.y += p.y; acc.z += p.z; acc.w += p.w;
    }
    float4 o;
    o.x = gelu_erf(acc.x); o.y = gelu_erf(acc.y);
    o.z = gelu_erf(acc.z); o.w = gelu_erf(acc.w);
    *(float4*)&g_h[(size_t)ent * DM + c4] = o;
}

// ---------------------------------------------------------------------------
// 4) Combine (stage-2 reduce + gate + residual + LN) + fused next-layer router
// ---------------------------------------------------------------------------
__global__ void k_combine(const float* __restrict__ gamma,
                          const float* __restrict__ beta,
                          const float* __restrict__ b2l,
                          const float* __restrict__ Wr_next,
                          int l_next, int do_route) {
    int r = blockIdx.x;
    int tid = threadIdx.x;
    __shared__ __align__(16) float red[36];
    __shared__ __align__(16) float xrow[DM];
    __shared__ __align__(16) float logits[NT];
    int c4 = tid * 4;

    float4 v = *(const float4*)&g_x[r * DM + c4];
#pragma unroll
    for (int k = 0; k < KSEL; k++) {
        int ent = r * 4 + k;
        int t = g_tile[ent];
        float gate = g_gate[ent];
        float4 acc = *(const float4*)&b2l[t * DM + c4];
#pragma unroll
        for (int s = 0; s < KSPLIT; s++) {
            float4 p = *(const float4*)&g_part[((size_t)s * NENT + ent) * DM + c4];
            acc.x += p.x; acc.y += p.y; acc.z += p.z; acc.w += p.w;
        }
        v.x += gate * acc.x; v.y += gate * acc.y;
        v.z += gate * acc.z; v.w += gate * acc.w;
    }
    float s = v.x + v.y + v.z + v.w;
    float mean = blockReduceSum(s, red) * (1.0f / DM);
    float dx = v.x - mean, dy = v.y - mean, dz = v.z - mean, dw = v.w - mean;
    float ss = dx * dx + dy * dy + dz * dz + dw * dw;
    float var = blockReduceSum(ss, red) * (1.0f / DM);
    float inv = rsqrtf(var + 1e-5f);

    float4 o;
    o.x = dx * inv * gamma[c4 + 0] + beta[c4 + 0];
    o.y = dy * inv * gamma[c4 + 1] + beta[c4 + 1];
    o.z = dz * inv * gamma[c4 + 2] + beta[c4 + 2];
    o.w = dw * inv * gamma[c4 + 3] + beta[c4 + 3];
    *(float4*)&g_x[r * DM + c4] = o;

    if (do_route) {
        *(float4*)&xrow[c4] = o;
        __syncthreads();
        route_row(r, l_next, Wr_next, xrow, logits);
    }
}

// ---------------------------------------------------------------------------
// 5) Heads layer-1
// ---------------------------------------------------------------------------
__global__ __launch_bounds__(256)
void k_heads1(const float* __restrict__ Ws1, const float* __restrict__ bs1,
              const float* __restrict__ Wd1, const float* __restrict__ bd1) {
    __shared__ __align__(16) float xsh[8][DM];
    int tid = threadIdx.x;
    int rbase = blockIdx.x * 8;

#pragma unroll
    for (int i = 0; i < 8; i++) {
        int idx = tid + i * 256;
        int row = idx >> 8;
        int c4 = (idx & 255) * 4;
        *(float4*)&xsh[row][c4] = *(const float4*)&g_x[(rbase + row) * DM + c4];
    }
    __syncthreads();

    const bool sumhead = tid < 128;
    const int j = blockIdx.y * 128 + (sumhead ? tid : tid - 128);
    const float* __restrict__ W = sumhead ? Ws1 : Wd1;
    float* __restrict__ outp = sumhead ? g_hs : g_hd;
    float bb = sumhead ? bs1[j] : bd1[j];

    float acc[8];
#pragma unroll
    for (int rr = 0; rr < 8; rr++) acc[rr] = bb;

    for (int d = 0; d < DM; d += 4) {
        float w0 = W[(d + 0) * 512 + j];
        float w1 = W[(d + 1) * 512 + j];
        float w2 = W[(d + 2) * 512 + j];
        float w3 = W[(d + 3) * 512 + j];
#pragma unroll
        for (int rr = 0; rr < 8; rr++) {
            float4 xv = *(const float4*)&xsh[rr][d];
            acc[rr] += xv.x * w0 + xv.y * w1 + xv.z * w2 + xv.w * w3;
        }
    }
#pragma unroll
    for (int rr = 0; rr < 8; rr++)
        outp[(rbase + rr) * 512 + j] = gelu_erf(acc[rr]);
}

// ---------------------------------------------------------------------------
// 6) Heads layer-2
// ---------------------------------------------------------------------------
__global__ void k_heads2(const float* __restrict__ Ws2, const float* __restrict__ bs2,
                         const float* __restrict__ Wd2, const float* __restrict__ bd2) {
    int r = blockIdx.x;
    int tid = threadIdx.x;
    int c = tid >> 5, lane = tid & 31;
    if (c >= 11) return;
    const float* h;
    const float* W;
    float bb; int nc, cc;
    if (c < 5) { h = g_hs + r * 512; W = Ws2; nc = 5; cc = c;     bb = bs2[c]; }
    else       { h = g_hd + r * 512; W = Wd2; nc = 6; cc = c - 5; bb = bd2[c - 5]; }
    float s = 0.0f;
#pragma unroll 4
    for (int f = lane; f < 512; f += 32) s += h[f] * W[f * nc + cc];
#pragma unroll
    for (int o = 16; o > 0; o >>= 1) s += __shfl_down_sync(0xffffffffu, s, o);
    if (lane == 0) g_table[r * 11 + c] = s + bb;
}

// ---------------------------------------------------------------------------
// 7) Gather
// ---------------------------------------------------------------------------
__global__ void k_output(const int* __restrict__ a, const int* __restrict__ b,
                         float* __restrict__ out, int total) {
    int idx = blockIdx.x * blockDim.x + threadIdx.x;
    if (idx >= total) return;
    int i = idx / 11;
    int c = idx - i * 11;
    int r = a[i] * 16 + b[i];
    out[idx] = g_table[r * 11 + c];
}

// ---------------------------------------------------------------------------
extern "C" void kernel_launch(void* const* d_in, const int* in_sizes, int n_in,
                              void* d_out, int out_size) {
    const int*   a      = (const int*)d_in[0];
    const int*   b      = (const int*)d_in[1];
    const float* Win    = (const float*)d_in[2];
    const float* bin_   = (const float*)d_in[3];
    const float* g_in   = (const float*)d_in[4];
    const float* b_ln   = (const float*)d_in[5];
    const float* Wr     = (const float*)d_in[6];
    const float* W1     = (const float*)d_in[7];
    const float* b1     = (const float*)d_in[8];
    const float* W2     = (const float*)d_in[9];
    const float* b2     = (const float*)d_in[10];
    const float* g_l    = (const float*)d_in[11];
    const float* b_l    = (const float*)d_in[12];
    const float* Ws1    = (const float*)d_in[13];
    const float* bs1    = (const float*)d_in[14];
    const float* Ws2    = (const float*)d_in[15];
    const float* bs2    = (const float*)d_in[16];
    const float* Wd1    = (const float*)d_in[17];
    const float* bd1    = (const float*)d_in[18];
    const float* Wd2    = (const float*)d_in[19];
    const float* bd2    = (const float*)d_in[20];
    float* out = (float*)d_out;

    (void)in_sizes; (void)n_in;

    k_zero<<<1, 64>>>();
    k_encode<<<NROWS, 256>>>(Win, bin_, g_in, b_ln, Wr);

    for (int l = 0; l < NL; l++) {
        dim3 gffn(DM / CB, NT, (NROWS / RG) * KSPLIT);
        k_ffn<1><<<gffn, 256>>>(W1 + (size_t)l * NT * DM * DM, l);
        k_red1<<<NENT, 256>>>(b1 + (size_t)l * NT * DM);
        k_ffn<2><<<gffn, 256>>>(W2 + (size_t)l * NT * DM * DM, l);
        int do_route = (l + 1 < NL) ? 1 : 0;
        const float* wrn = Wr + (size_t)(l + 1 < NL ? l + 1 : 0) * DM * NT;
        k_combine<<<NROWS, 256>>>(g_l + (size_t)l * DM, b_l + (size_t)l * DM,
                                  b2 + (size_t)l * NT * DM, wrn, l + 1, do_route);
    }

    k_heads1<<<dim3(NROWS / 8, 4), 256>>>(Ws1, bs1, Wd1, bd1);
    k_heads2<<<NROWS, 352>>>(Ws2, bs2, Wd2, bd2);

    int total = out_size;
    k_output<<<(total + 255) / 256, 256>>>(a, b, out, total);
}